// round 3
// baseline (speedup 1.0000x reference)
#include <cuda_runtime.h>
#include <cuda_bf16.h>
#include <math.h>

#define B_  32
#define S_  512
#define E_  256
#define H_  8
#define DH_ 32
#define L_  4
#define FF_ 1024
#define BS_ (B_ * S_)          // 16384 rows
#define EPS_ 1e-5f

// ---------------- scratch (allocation-free: __device__ globals) ----------------
__device__ float g_h  [BS_ * E_];
__device__ float g_xn [BS_ * E_];
__device__ float g_q  [BS_ * E_];
__device__ float g_k  [BS_ * E_];
__device__ float g_v  [BS_ * E_];
__device__ float g_att[BS_ * E_];
__device__ float g_res[BS_ * E_];
__device__ float g_rn [BS_ * E_];
__device__ float g_ff [BS_ * FF_];

// ---------------- helpers ----------------
__device__ __forceinline__ float block_reduce_sum_256(float v, float* sbuf) {
    int lane = threadIdx.x & 31, wid = threadIdx.x >> 5;
    #pragma unroll
    for (int o = 16; o; o >>= 1) v += __shfl_xor_sync(0xffffffffu, v, o);
    if (lane == 0) sbuf[wid] = v;
    __syncthreads();
    if (wid == 0) {
        v = (lane < 8) ? sbuf[lane] : 0.f;
        #pragma unroll
        for (int o = 4; o; o >>= 1) v += __shfl_xor_sync(0xffffffffu, v, o);
        if (lane == 0) sbuf[0] = v;
    }
    __syncthreads();
    v = sbuf[0];
    __syncthreads();   // sbuf reused by caller
    return v;
}

// ---------------- kernels ----------------

// h = x + pos  (pos broadcast over last dim E)
__global__ void k_addpos(const float* __restrict__ x, const float* __restrict__ pos) {
    int i = blockIdx.x * blockDim.x + threadIdx.x;
    g_h[i] = x[i] + pos[i & (E_ - 1)];
}

// dst = LayerNorm(src), one block (256 threads) per row
__global__ __launch_bounds__(256) void k_ln(const float* __restrict__ src,
                                            float* __restrict__ dst) {
    __shared__ float sbuf[8];
    int row = blockIdx.x;
    float x = src[row * E_ + threadIdx.x];
    float m = block_reduce_sum_256(x, sbuf) * (1.0f / E_);
    float d = x - m;
    float v = block_reduce_sum_256(d * d, sbuf) * (1.0f / E_);
    dst[row * E_ + threadIdx.x] = d * rsqrtf(v + EPS_);
}

// res = a + b ; rn = LayerNorm(res)
__global__ __launch_bounds__(256) void k_add_ln(const float* __restrict__ a,
                                                const float* __restrict__ b,
                                                float* __restrict__ res,
                                                float* __restrict__ rn) {
    __shared__ float sbuf[8];
    int row = blockIdx.x;
    int i = row * E_ + threadIdx.x;
    float x = a[i] + b[i];
    res[i] = x;
    float m = block_reduce_sum_256(x, sbuf) * (1.0f / E_);
    float d = x - m;
    float v = block_reduce_sum_256(d * d, sbuf) * (1.0f / E_);
    rn[i] = d * rsqrtf(v + EPS_);
}

// QKV projection: per (b,h): q/k/v[s, :] = xn[s, h*32:+32] @ W{q,k,v}[h]  (32x32)
// grid: (S/64, B*H), 256 threads. q pre-scaled by 1/sqrt(DH).
__global__ __launch_bounds__(256) void k_qkv(const float* __restrict__ xn,
                                             const float* __restrict__ Wq,
                                             const float* __restrict__ Wk,
                                             const float* __restrict__ Wv) {
    __shared__ __align__(16) float Xs[64 * 32];
    __shared__ __align__(16) float WsQ[32 * 32];
    __shared__ __align__(16) float WsK[32 * 32];
    __shared__ __align__(16) float WsV[32 * 32];
    int tid = threadIdx.x;
    int bh = blockIdx.y;
    int b = bh >> 3, h = bh & 7;
    int s0 = blockIdx.x * 64;

    ((float4*)WsQ)[tid] = ((const float4*)(Wq + h * 1024))[tid];
    ((float4*)WsK)[tid] = ((const float4*)(Wk + h * 1024))[tid];
    ((float4*)WsV)[tid] = ((const float4*)(Wv + h * 1024))[tid];
    #pragma unroll
    for (int it = 0; it < 2; it++) {
        int fi = it * 256 + tid;        // 512 float4 total
        int r = fi >> 3, d4 = fi & 7;
        float4 t = *(const float4*)(xn + (b * S_ + s0 + r) * E_ + h * 32 + d4 * 4);
        *(float4*)(Xs + r * 32 + d4 * 4) = t;
    }
    __syncthreads();

    int w = tid >> 5, lane = tid & 31;
    int r0 = w * 8;
    float aq[8] = {0}, ak[8] = {0}, av[8] = {0};
    #pragma unroll
    for (int d = 0; d < 32; d++) {
        float wq = WsQ[d * 32 + lane];
        float wk = WsK[d * 32 + lane];
        float wv = WsV[d * 32 + lane];
        #pragma unroll
        for (int r = 0; r < 8; r++) {
            float xv = Xs[(r0 + r) * 32 + d];
            aq[r] = fmaf(xv, wq, aq[r]);
            ak[r] = fmaf(xv, wk, ak[r]);
            av[r] = fmaf(xv, wv, av[r]);
        }
    }
    const float qs = 0.17677669529663687f;  // 1/sqrt(32)
    #pragma unroll
    for (int r = 0; r < 8; r++) {
        int idx = (bh * S_ + s0 + r0 + r) * DH_ + lane;   // layout (b,h,s,d)
        g_q[idx] = aq[r] * qs;
        g_k[idx] = ak[r];
        g_v[idx] = av[r];
    }
}

// Flash attention: grid (S/64, B*H), 256 threads (16x16 thread tile).
// Q pre-scaled. Output written to g_att in (b,s,h,d) layout (= concat heads).
__global__ __launch_bounds__(256) void k_attn() {
    __shared__ __align__(16) float Qs[64 * 32];
    __shared__ __align__(16) float Ks[64 * 33];   // padded: scored by column
    __shared__ __align__(16) float Vs[64 * 32];
    __shared__ __align__(16) float Ps[64 * 64];
    int tid = threadIdx.x;
    int tx = tid & 15, ty = tid >> 4;
    int bh = blockIdx.y;
    int s0 = blockIdx.x * 64;
    int i0 = ty * 4;

    const float* qp = g_q + (bh * S_ + s0) * DH_;
    #pragma unroll
    for (int it = 0; it < 2; it++) {
        int fi = it * 256 + tid;
        int r = fi >> 3, d4 = fi & 7;
        *(float4*)(Qs + r * 32 + d4 * 4) = *(const float4*)(qp + r * 32 + d4 * 4);
    }

    float m[4], l[4], o[4][2];
    #pragma unroll
    for (int a = 0; a < 4; a++) { m[a] = -1e30f; l[a] = 0.f; o[a][0] = 0.f; o[a][1] = 0.f; }

    for (int kb = 0; kb < S_ / 64; kb++) {
        __syncthreads();   // previous AV readers done with Ks/Vs
        const float* kp = g_k + (bh * S_ + kb * 64) * DH_;
        const float* vp = g_v + (bh * S_ + kb * 64) * DH_;
        #pragma unroll
        for (int it = 0; it < 8; it++) {
            int e = it * 256 + tid;
            Ks[(e >> 5) * 33 + (e & 31)] = kp[e];
        }
        #pragma unroll
        for (int it = 0; it < 2; it++) {
            int fi = it * 256 + tid;
            int r = fi >> 3, d4 = fi & 7;
            *(float4*)(Vs + r * 32 + d4 * 4) = *(const float4*)(vp + r * 32 + d4 * 4);
        }
        __syncthreads();

        // scores 4x4 micro-tile
        float sc[4][4];
        #pragma unroll
        for (int a = 0; a < 4; a++)
            #pragma unroll
            for (int bb = 0; bb < 4; bb++) sc[a][bb] = 0.f;
        #pragma unroll
        for (int d = 0; d < 32; d++) {
            float qv[4], kv[4];
            #pragma unroll
            for (int a = 0; a < 4; a++) qv[a] = Qs[(i0 + a) * 32 + d];
            #pragma unroll
            for (int bb = 0; bb < 4; bb++) kv[bb] = Ks[(tx * 4 + bb) * 33 + d];
            #pragma unroll
            for (int a = 0; a < 4; a++)
                #pragma unroll
                for (int bb = 0; bb < 4; bb++) sc[a][bb] = fmaf(qv[a], kv[bb], sc[a][bb]);
        }

        // online softmax per row (reduced across the 16 tx threads = half-warp)
        float rescale[4];
        #pragma unroll
        for (int a = 0; a < 4; a++) {
            float tm = fmaxf(fmaxf(sc[a][0], sc[a][1]), fmaxf(sc[a][2], sc[a][3]));
            #pragma unroll
            for (int off = 8; off; off >>= 1)
                tm = fmaxf(tm, __shfl_xor_sync(0xffffffffu, tm, off));
            float mn = fmaxf(m[a], tm);
            float so = __expf(m[a] - mn);
            float p0 = __expf(sc[a][0] - mn);
            float p1 = __expf(sc[a][1] - mn);
            float p2 = __expf(sc[a][2] - mn);
            float p3 = __expf(sc[a][3] - mn);
            float ts = p0 + p1 + p2 + p3;
            #pragma unroll
            for (int off = 8; off; off >>= 1)
                ts += __shfl_xor_sync(0xffffffffu, ts, off);
            l[a] = l[a] * so + ts;
            m[a] = mn;
            rescale[a] = so;
            *(float4*)&Ps[(i0 + a) * 64 + tx * 4] = make_float4(p0, p1, p2, p3);
        }
        #pragma unroll
        for (int a = 0; a < 4; a++) { o[a][0] *= rescale[a]; o[a][1] *= rescale[a]; }
        __syncthreads();

        // o += P @ V  (thread covers rows i0..i0+3, dims 2*tx, 2*tx+1)
        #pragma unroll 8
        for (int j = 0; j < 64; j++) {
            float2 vv = *(float2*)&Vs[j * 32 + tx * 2];
            #pragma unroll
            for (int a = 0; a < 4; a++) {
                float pv = Ps[(i0 + a) * 64 + j];
                o[a][0] = fmaf(pv, vv.x, o[a][0]);
                o[a][1] = fmaf(pv, vv.y, o[a][1]);
            }
        }
    }

    int b = bh >> 3, h = bh & 7;
    #pragma unroll
    for (int a = 0; a < 4; a++) {
        float inv = 1.0f / l[a];
        int s = s0 + i0 + a;
        float* op = g_att + (b * S_ + s) * E_ + h * 32 + tx * 2;
        op[0] = o[a][0] * inv;
        op[1] = o[a][1] * inv;
    }
}

// FFN1: g_ff = gelu(rn @ W1 + b1).  grid (FF/64, BS/64), 256 thr, 64x64 tile, K=256.
__global__ __launch_bounds__(256) void k_ffn1(const float* __restrict__ A,
                                              const float* __restrict__ W,
                                              const float* __restrict__ bias) {
    __shared__ __align__(16) float As[64 * 32];
    __shared__ __align__(16) float Bs[32 * 68];
    int tid = threadIdx.x, tx = tid & 15, ty = tid >> 4;
    int n0 = blockIdx.x * 64, m0 = blockIdx.y * 64;
    float acc[4][4];
    #pragma unroll
    for (int a = 0; a < 4; a++)
        #pragma unroll
        for (int bb = 0; bb < 4; bb++) acc[a][bb] = 0.f;

    for (int kt = 0; kt < E_ / 32; kt++) {
        __syncthreads();
        #pragma unroll
        for (int it = 0; it < 2; it++) {
            int fi = it * 256 + tid;
            int r = fi >> 3, d4 = fi & 7;
            *(float4*)(As + r * 32 + d4 * 4) =
                *(const float4*)(A + (m0 + r) * E_ + kt * 32 + d4 * 4);
        }
        #pragma unroll
        for (int it = 0; it < 2; it++) {
            int fi = it * 256 + tid;
            int kk = fi >> 4, j4 = fi & 15;
            *(float4*)(Bs + kk * 68 + j4 * 4) =
                *(const float4*)(W + (kt * 32 + kk) * FF_ + n0 + j4 * 4);
        }
        __syncthreads();
        #pragma unroll
        for (int kk = 0; kk < 32; kk++) {
            float a4[4];
            #pragma unroll
            for (int a = 0; a < 4; a++) a4[a] = As[(ty * 4 + a) * 32 + kk];
            float4 b4 = *(float4*)&Bs[kk * 68 + tx * 4];
            #pragma unroll
            for (int a = 0; a < 4; a++) {
                acc[a][0] = fmaf(a4[a], b4.x, acc[a][0]);
                acc[a][1] = fmaf(a4[a], b4.y, acc[a][1]);
                acc[a][2] = fmaf(a4[a], b4.z, acc[a][2]);
                acc[a][3] = fmaf(a4[a], b4.w, acc[a][3]);
            }
        }
    }
    float4 bb4 = *(const float4*)&bias[n0 + tx * 4];
    const float isq2 = 0.7071067811865476f;
    #pragma unroll
    for (int a = 0; a < 4; a++) {
        int row = m0 + ty * 4 + a;
        float c0 = acc[a][0] + bb4.x, c1 = acc[a][1] + bb4.y;
        float c2 = acc[a][2] + bb4.z, c3 = acc[a][3] + bb4.w;
        float4 g;
        g.x = 0.5f * c0 * (1.0f + erff(c0 * isq2));
        g.y = 0.5f * c1 * (1.0f + erff(c1 * isq2));
        g.z = 0.5f * c2 * (1.0f + erff(c2 * isq2));
        g.w = 0.5f * c3 * (1.0f + erff(c3 * isq2));
        *(float4*)(g_ff + row * FF_ + n0 + tx * 4) = g;
    }
}

// FFN2 + residual: out = g_ff @ W2 + b2 + res.  grid (E/64, BS/64), K=1024.
__global__ __launch_bounds__(256) void k_ffn2(const float* __restrict__ W,
                                              const float* __restrict__ bias,
                                              const float* __restrict__ res,
                                              float* __restrict__ out) {
    __shared__ __align__(16) float As[64 * 32];
    __shared__ __align__(16) float Bs[32 * 68];
    int tid = threadIdx.x, tx = tid & 15, ty = tid >> 4;
    int n0 = blockIdx.x * 64, m0 = blockIdx.y * 64;
    float acc[4][4];
    #pragma unroll
    for (int a = 0; a < 4; a++)
        #pragma unroll
        for (int bb = 0; bb < 4; bb++) acc[a][bb] = 0.f;

    for (int kt = 0; kt < FF_ / 32; kt++) {
        __syncthreads();
        #pragma unroll
        for (int it = 0; it < 2; it++) {
            int fi = it * 256 + tid;
            int r = fi >> 3, d4 = fi & 7;
            *(float4*)(As + r * 32 + d4 * 4) =
                *(const float4*)(g_ff + (m0 + r) * FF_ + kt * 32 + d4 * 4);
        }
        #pragma unroll
        for (int it = 0; it < 2; it++) {
            int fi = it * 256 + tid;
            int kk = fi >> 4, j4 = fi & 15;
            *(float4*)(Bs + kk * 68 + j4 * 4) =
                *(const float4*)(W + (kt * 32 + kk) * E_ + n0 + j4 * 4);
        }
        __syncthreads();
        #pragma unroll
        for (int kk = 0; kk < 32; kk++) {
            float a4[4];
            #pragma unroll
            for (int a = 0; a < 4; a++) a4[a] = As[(ty * 4 + a) * 32 + kk];
            float4 b4 = *(float4*)&Bs[kk * 68 + tx * 4];
            #pragma unroll
            for (int a = 0; a < 4; a++) {
                acc[a][0] = fmaf(a4[a], b4.x, acc[a][0]);
                acc[a][1] = fmaf(a4[a], b4.y, acc[a][1]);
                acc[a][2] = fmaf(a4[a], b4.z, acc[a][2]);
                acc[a][3] = fmaf(a4[a], b4.w, acc[a][3]);
            }
        }
    }
    float4 bb4 = *(const float4*)&bias[n0 + tx * 4];
    #pragma unroll
    for (int a = 0; a < 4; a++) {
        int row = m0 + ty * 4 + a;
        float4 r4 = *(const float4*)(res + row * E_ + n0 + tx * 4);
        float4 g;
        g.x = acc[a][0] + bb4.x + r4.x;
        g.y = acc[a][1] + bb4.y + r4.y;
        g.z = acc[a][2] + bb4.z + r4.z;
        g.w = acc[a][3] + bb4.w + r4.w;
        *(float4*)(out + row * E_ + n0 + tx * 4) = g;
    }
}

// ---------------- launch ----------------
extern "C" void kernel_launch(void* const* d_in, const int* in_sizes, int n_in,
                              void* d_out, int out_size) {
    const float* x   = (const float*)d_in[0];
    const float* pos = (const float*)d_in[1];
    const float* Wq  = (const float*)d_in[2];
    const float* Wk  = (const float*)d_in[3];
    const float* Wv  = (const float*)d_in[4];
    const float* W1  = (const float*)d_in[5];
    const float* b1  = (const float*)d_in[6];
    const float* W2  = (const float*)d_in[7];
    const float* b2  = (const float*)d_in[8];
    float* out = (float*)d_out;

    float *ph, *pxn, *patt, *pres, *prn;
    cudaGetSymbolAddress((void**)&ph,   g_h);
    cudaGetSymbolAddress((void**)&pxn,  g_xn);
    cudaGetSymbolAddress((void**)&patt, g_att);
    cudaGetSymbolAddress((void**)&pres, g_res);
    cudaGetSymbolAddress((void**)&prn,  g_rn);

    k_addpos<<<BS_ * E_ / 256, 256>>>(x, pos);

    for (int l = 0; l < L_; l++) {
        const float* wq = Wq + l * H_ * DH_ * DH_;
        const float* wk = Wk + l * H_ * DH_ * DH_;
        const float* wv = Wv + l * H_ * DH_ * DH_;
        const float* w1 = W1 + l * E_ * FF_;
        const float* bb1 = b1 + l * FF_;
        const float* w2 = W2 + l * FF_ * E_;
        const float* bb2 = b2 + l * E_;
        float* hout = (l == L_ - 1) ? out : ph;

        k_ln<<<BS_, 256>>>(ph, pxn);
        k_qkv<<<dim3(S_ / 64, B_ * H_), 256>>>(pxn, wq, wk, wv);
        k_attn<<<dim3(S_ / 64, B_ * H_), 256>>>();
        k_add_ln<<<BS_, 256>>>(patt, ph, pres, prn);
        k_ffn1<<<dim3(FF_ / 64, BS_ / 64), 256>>>(prn, w1, bb1);
        k_ffn2<<<dim3(E_ / 64, BS_ / 64), 256>>>(w2, bb2, pres, hout);
    }
}